// round 1
// baseline (speedup 1.0000x reference)
#include <cuda_runtime.h>

#define NXd 24
#define NUd 8
#define NNd 32
#define Td  100
#define Bd  512
#define NTHREADS 128
#define REGU 1e-6f

// Global scratch for gains (41 MB total -> L2-resident). __device__ globals are
// the allowed scratch mechanism (no runtime allocation).
__device__ float g_K[(size_t)Bd * Td * NUd * NXd];
__device__ float g_kv[(size_t)Bd * Td * NUd];

__global__ __launch_bounds__(NTHREADS, 4)
void lqr_kernel(const float* __restrict__ x0g,
                const float* __restrict__ Cm,
                const float* __restrict__ cv,
                const float* __restrict__ Cf,
                const float* __restrict__ cf,
                const float* __restrict__ xref,
                const float* __restrict__ uref,
                const float* __restrict__ Ad,
                const float* __restrict__ Bdyn,
                float* __restrict__ out)
{
    // F = [A | B] : F[k][m], k<24, m<32.
    __shared__ __align__(16) float Fs[NXd][NNd];   // F row-major   (lane-varying m contiguous)
    __shared__ __align__(16) float Ft[NNd][NXd];   // F^T row-major (bcast float4 over k)
    __shared__ __align__(16) float V[NXd][NXd];    // value matrix (symmetric)
    __shared__ __align__(16) float Vtmp[NXd][NXd];
    __shared__ __align__(16) float VF[NXd][NNd];   // V * F
    __shared__ __align__(16) float G[NNd][NNd];    // C_t + F^T V F (+ reg on uu diag)
    __shared__ __align__(16) float zref[NNd];
    __shared__ __align__(16) float qs[NNd];
    __shared__ __align__(16) float Qxq[NNd];       // [Qx (24) | Qu (8)]
    __shared__ __align__(16) float vS[NXd];
    __shared__ __align__(16) float Minv[NUd][NUd]; // Quu^{-1}
    __shared__ __align__(16) float Kt[NUd][NXd];
    __shared__ __align__(16) float kvt[NUd];

    const int b    = blockIdx.x;
    const int tid  = threadIdx.x;
    const int wid  = tid >> 5;
    const int lane = tid & 31;

    // ---- init: F copies ----
    for (int o = tid; o < NXd * NNd; o += NTHREADS) {
        int k = o >> 5, m = o & 31;
        float val = (m < NXd) ? Ad[k * NXd + m] : Bdyn[k * NUd + (m - NXd)];
        Fs[k][m] = val;
        Ft[m][k] = val;
    }
    // ---- init: V = C_final[:24,:24] ----
    for (int o = tid; o < NXd * NXd; o += NTHREADS) {
        int i = o / NXd, j = o - i * NXd;
        V[i][j] = Cf[((size_t)b * NNd + i) * NNd + j];
    }
    // ---- zref for t = T-1 ----
    if (tid < NNd) {
        int j = tid;
        zref[j] = (j < NXd) ? xref[((size_t)b * (Td + 1) + (Td - 1)) * NXd + j]
                            : uref[((size_t)b * Td + (Td - 1)) * NUd + (j - NXd)];
    }
    __syncthreads();
    // ---- v_T = c_final[:24] - V @ x_ref[:,T] ----
    if (tid < NXd) {
        float acc = cf[(size_t)b * NNd + tid];
        const float* xl = xref + ((size_t)b * (Td + 1) + Td) * NXd;
        #pragma unroll
        for (int j = 0; j < NXd; j++) acc -= V[tid][j] * xl[j];
        vS[tid] = acc;
    }
    __syncthreads();

    // ================= backward Riccati =================
    for (int t = Td - 1; t >= 0; t--) {
        const float* Cb = Cm + ((size_t)b * Td + t) * NNd * NNd;

        // ---- P1: VF[i][m] = sum_k V[i][k] F[k][m]  ;  q[m] = c[m] - sum_j C[m][j] z[j]
        // (C is exactly symmetric by construction -> read column-coalesced)
        for (int tau = wid; tau < NXd + 1; tau += 4) {
            if (tau < NXd) {
                const int i = tau, m = lane;
                const float4* Vrow = (const float4*)&V[i][0];
                float acc = 0.f;
                #pragma unroll
                for (int k4 = 0; k4 < 6; k4++) {
                    float4 vv = Vrow[k4];
                    acc += vv.x * Fs[4 * k4 + 0][m];
                    acc += vv.y * Fs[4 * k4 + 1][m];
                    acc += vv.z * Fs[4 * k4 + 2][m];
                    acc += vv.w * Fs[4 * k4 + 3][m];
                }
                VF[i][m] = acc;
            } else {
                const int m = lane;
                float acc = cv[((size_t)b * Td + t) * NNd + m];
                const float4* z4 = (const float4*)zref;
                #pragma unroll
                for (int j4 = 0; j4 < 8; j4++) {
                    float4 z = z4[j4];
                    acc -= z.x * Cb[(4 * j4 + 0) * NNd + m];
                    acc -= z.y * Cb[(4 * j4 + 1) * NNd + m];
                    acc -= z.z * Cb[(4 * j4 + 2) * NNd + m];
                    acc -= z.w * Cb[(4 * j4 + 3) * NNd + m];
                }
                qs[m] = acc;
            }
        }
        __syncthreads();

        // ---- P2: G[m][n] = C[m][n] + sum_k Ft[m][k] VF[k][n] (+reg)  ;  Qxq = q + F^T v
        for (int tau = wid; tau < NNd + 1; tau += 4) {
            if (tau < NNd) {
                const int m = tau, n = lane;
                const float4* Frow = (const float4*)&Ft[m][0];
                float acc = Cb[m * NNd + n];
                #pragma unroll
                for (int k4 = 0; k4 < 6; k4++) {
                    float4 f = Frow[k4];
                    acc += f.x * VF[4 * k4 + 0][n];
                    acc += f.y * VF[4 * k4 + 1][n];
                    acc += f.z * VF[4 * k4 + 2][n];
                    acc += f.w * VF[4 * k4 + 3][n];
                }
                if (m >= NXd && n == m) acc += REGU;
                G[m][n] = acc;
            } else {
                const int n = lane;
                float acc = qs[n];
                const float4* v4 = (const float4*)vS;
                #pragma unroll
                for (int k4 = 0; k4 < 6; k4++) {
                    float4 vv = v4[k4];
                    acc += vv.x * Fs[4 * k4 + 0][n];
                    acc += vv.y * Fs[4 * k4 + 1][n];
                    acc += vv.z * Fs[4 * k4 + 2][n];
                    acc += vv.w * Fs[4 * k4 + 3][n];
                }
                Qxq[n] = acc;
            }
        }
        __syncthreads();

        // ---- P3+P4 (warp 0): register Gauss-Jordan inverse of Quu (SPD, no pivoting),
        //      then K = -Minv*Qux, kv = -Minv*Qu
        if (wid == 0) {
            const unsigned FULL = 0xffffffffu;
            const int r = lane >> 2, cb = lane & 3;  // lane owns row r, cols {cb,cb+4,cb+8,cb+12} of [Quu|I]
            float a[4];
            a[0] = G[NXd + r][NXd + cb];
            a[1] = G[NXd + r][NXd + cb + 4];
            a[2] = (cb == r)     ? 1.f : 0.f;
            a[3] = (cb + 4 == r) ? 1.f : 0.f;
            #pragma unroll
            for (int k = 0; k < 8; k++) {
                float piv  = __shfl_sync(FULL, a[k >> 2], 4 * k + (k & 3));
                float pinv = 1.0f / piv;
                if (r == k) { a[0] *= pinv; a[1] *= pinv; a[2] *= pinv; a[3] *= pinv; }
                float rk0 = __shfl_sync(FULL, a[0], 4 * k + cb);
                float rk1 = __shfl_sync(FULL, a[1], 4 * k + cb);
                float rk2 = __shfl_sync(FULL, a[2], 4 * k + cb);
                float rk3 = __shfl_sync(FULL, a[3], 4 * k + cb);
                float f   = __shfl_sync(FULL, a[k >> 2], 4 * r + (k & 3)); // pre-elim Aug[r][k]
                if (r != k) { a[0] -= f * rk0; a[1] -= f * rk1; a[2] -= f * rk2; a[3] -= f * rk3; }
            }
            Minv[r][cb]     = a[2];
            Minv[r][cb + 4] = a[3];
            __syncwarp();
            for (int o = lane; o < NUd * NXd + NUd; o += 32) {
                if (o < NUd * NXd) {
                    int l = o / NXd, j = o - l * NXd;
                    float acc = 0.f;
                    #pragma unroll
                    for (int mm = 0; mm < NUd; mm++) acc += Minv[l][mm] * G[NXd + mm][j];
                    float kk = -acc;
                    Kt[l][j] = kk;
                    g_K[(((size_t)b * Td + t) * NUd + l) * NXd + j] = kk;
                } else {
                    int l = o - NUd * NXd;
                    float acc = 0.f;
                    #pragma unroll
                    for (int mm = 0; mm < NUd; mm++) acc += Minv[l][mm] * Qxq[NXd + mm];
                    kvt[l] = -acc;
                    g_kv[((size_t)b * Td + t) * NUd + l] = -acc;
                }
            }
        }
        __syncthreads();

        // ---- P5: Vtmp = Qxx + Qux^T K  ;  v = Qx + Qux^T kv
        for (int tau = wid; tau < NXd + 1; tau += 4) {
            if (tau < NXd) {
                const int i = tau, j = lane;
                if (j < NXd) {
                    float acc = G[i][j];
                    #pragma unroll
                    for (int l = 0; l < NUd; l++) acc += G[NXd + l][i] * Kt[l][j];
                    Vtmp[i][j] = acc;
                }
            } else {
                if (lane < NXd) {
                    float acc = Qxq[lane];
                    #pragma unroll
                    for (int l = 0; l < NUd; l++) acc += G[NXd + l][lane] * kvt[l];
                    vS[lane] = acc;  // safe: vS only read in P2 (already past)
                }
            }
        }
        __syncthreads();

        // ---- P6: symmetrize V, prefetch next zref
        for (int o = tid; o < NXd * NXd; o += NTHREADS) {
            int i = o / NXd, j = o - i * NXd;
            V[i][j] = 0.5f * (Vtmp[i][j] + Vtmp[j][i]);
        }
        if (t > 0 && tid < NNd) {
            int j = tid;
            zref[j] = (j < NXd) ? xref[((size_t)b * (Td + 1) + (t - 1)) * NXd + j]
                                : uref[((size_t)b * Td + (t - 1)) * NUd + (j - NXd)];
        }
        __syncthreads();
    }

    // ================= forward rollout (warp 0) =================
    if (wid == 0) {
        const unsigned FULL = 0xffffffffu;
        float* ob = out + (size_t)b * ((Td + 1) * NXd + Td * NUd);
        float xv = (lane < NXd) ? x0g[(size_t)b * NXd + lane] : 0.f;
        for (int t = 0; t < Td; t++) {
            if (lane < NXd) ob[t * NXd + lane] = xv;
            // u = K x + k  (lanes 8..31 compute duplicates of lane&7)
            const int l = lane & 7;
            const float* Krow = g_K + (((size_t)b * Td + t) * NUd + l) * NXd;
            float u = g_kv[((size_t)b * Td + t) * NUd + l];
            #pragma unroll
            for (int k = 0; k < NXd; k++) u += Krow[k] * __shfl_sync(FULL, xv, k);
            if (lane < NUd) ob[(Td + 1) * NXd + t * NUd + lane] = u;
            // x' = A x + B u   (A[i][k] = Ft[k][i], B[i][l] = Ft[24+l][i])
            const int i = (lane < NXd) ? lane : 0;
            float acc = 0.f;
            #pragma unroll
            for (int k = 0; k < NXd; k++) acc += Ft[k][i] * __shfl_sync(FULL, xv, k);
            #pragma unroll
            for (int l2 = 0; l2 < NUd; l2++) acc += Ft[NXd + l2][i] * __shfl_sync(FULL, u, l2);
            xv = acc;
        }
        if (lane < NXd) ob[Td * NXd + lane] = xv;
    }
}

extern "C" void kernel_launch(void* const* d_in, const int* in_sizes, int n_in,
                              void* d_out, int out_size)
{
    // Identify inputs by element count (all distinct); fall back to positional order.
    const float *x0 = nullptr, *C = nullptr, *c = nullptr, *Cf = nullptr, *cf = nullptr;
    const float *xr = nullptr, *ur = nullptr, *A = nullptr, *B = nullptr;
    for (int i = 0; i < n_in; i++) {
        const float* p = (const float*)d_in[i];
        switch (in_sizes[i]) {
            case 512 * 24:              x0 = p; break;   // 12288
            case 512 * 100 * 32 * 32:   C  = p; break;   // 52,428,800
            case 512 * 100 * 32:        c  = p; break;   // 1,638,400
            case 512 * 32 * 32:         Cf = p; break;   // 524,288
            case 512 * 32:              cf = p; break;   // 16,384
            case 512 * 101 * 24:        xr = p; break;   // 1,241,088
            case 512 * 100 * 8:         ur = p; break;   // 409,600
            case 24 * 24:               A  = p; break;   // 576
            case 24 * 8:                B  = p; break;   // 192
            default: break;
        }
    }
    if (!x0 || !C || !c || !Cf || !cf || !xr || !ur || !A || !B) {
        x0 = (const float*)d_in[0]; C  = (const float*)d_in[1];
        c  = (const float*)d_in[2]; Cf = (const float*)d_in[3];
        cf = (const float*)d_in[4]; xr = (const float*)d_in[5];
        ur = (const float*)d_in[6]; A  = (const float*)d_in[7];
        B  = (const float*)d_in[8];
    }
    lqr_kernel<<<Bd, NTHREADS>>>(x0, C, c, Cf, cf, xr, ur, A, B, (float*)d_out);
}

// round 3
// speedup vs baseline: 1.5731x; 1.5731x over previous
#include <cuda_runtime.h>

#define NXd 24
#define NUd 8
#define NNd 32
#define Td  100
#define Bd  512
#define NTHREADS 128
#define REGU 1e-6f

// Global scratch for gains (41 MB -> L2-resident). __device__ globals are the
// allowed scratch mechanism (no runtime allocation).
__device__ float g_K[(size_t)Bd * Td * NUd * NXd];
__device__ float g_kv[(size_t)Bd * Td * NUd];

__global__ __launch_bounds__(NTHREADS, 4)
void lqr_kernel(const float* __restrict__ x0g,
                const float* __restrict__ Cm,
                const float* __restrict__ cv,
                const float* __restrict__ Cf,
                const float* __restrict__ cf,
                const float* __restrict__ xref,
                const float* __restrict__ uref,
                const float* __restrict__ Ad,
                const float* __restrict__ Bdyn,
                float* __restrict__ out)
{
    // F = [A | B] : F[k][m], k<24, m<32.
    __shared__ __align__(16) float Ft[NNd][NXd];    // Ft[m][k] = F[k][m] (rows 96B, 16B aligned)
    __shared__ __align__(16) float V[NXd][NXd];     // value matrix (symmetric)
    __shared__ __align__(16) float Vtmp[NXd][NXd];
    __shared__ __align__(16) float VF[NXd][NNd];    // V * F
    __shared__ __align__(16) float G[NNd][NNd];     // C_t + F^T V F (+ reg on uu diag)
    __shared__ __align__(16) float QuxT[NXd][NUd];  // QuxT[j][l] = G[24+l][j]
    __shared__ __align__(16) float zS[NNd];
    __shared__ __align__(16) float qpart[4][NNd];
    __shared__ __align__(16) float Qxq[NNd];        // [Qx (24) | Qu (8)]
    __shared__ __align__(16) float vS[NXd];
    __shared__ __align__(16) float Minv[NUd][NUd];  // Quu^{-1}
    __shared__ __align__(16) float Kt[NUd][NXd];
    __shared__ __align__(16) float kvt[NUd];

    const int b    = blockIdx.x;
    const int tid  = threadIdx.x;
    const int wid  = tid >> 5;
    const int lane = tid & 31;

    // ---- register-resident F column: Fcol[k] = F[k][lane] ----
    float Fcol[NXd];
    #pragma unroll
    for (int k = 0; k < NXd; k++)
        Fcol[k] = (lane < NXd) ? Ad[k * NXd + lane] : Bdyn[k * NUd + (lane - NXd)];

    // ---- init: Ft smem (used for G row broadcasts + rollout) ----
    for (int o = tid; o < NXd * NNd; o += NTHREADS) {
        int k = o >> 5, m = o & 31;
        Ft[m][k] = (m < NXd) ? Ad[k * NXd + m] : Bdyn[k * NUd + (m - NXd)];
    }
    // ---- init: V = C_final[:24,:24] ----
    for (int o = tid; o < NXd * NXd; o += NTHREADS) {
        int i = o / NXd, j = o - i * NXd;
        V[i][j] = Cf[((size_t)b * NNd + i) * NNd + j];
    }
    // ---- zref for t = T-1 ----
    if (tid < NNd) {
        int j = tid;
        zS[j] = (j < NXd) ? xref[((size_t)b * (Td + 1) + (Td - 1)) * NXd + j]
                          : uref[((size_t)b * Td + (Td - 1)) * NUd + (j - NXd)];
    }
    __syncthreads();
    // ---- v_T = c_final[:24] - V @ x_ref[:,T] ----
    if (tid < NXd) {
        float acc = cf[(size_t)b * NNd + tid];
        const float* xl = xref + ((size_t)b * (Td + 1) + Td) * NXd;
        #pragma unroll
        for (int j = 0; j < NXd; j++) acc -= V[tid][j] * xl[j];
        vS[tid] = acc;
    }
    __syncthreads();

    // ================= backward Riccati =================
    for (int t = Td - 1; t >= 0; t--) {
        const float* Cb = Cm + ((size_t)b * Td + t) * NNd * NNd;

        // ---- Phase A: VF[i][m] = sum_k V[i][k] * F[k][m] (Fcol in regs) ----
        for (int i = wid; i < NXd; i += 4) {
            const float4* Vr = (const float4*)&V[i][0];
            float acc = 0.f;
            #pragma unroll
            for (int k4 = 0; k4 < 6; k4++) {
                float4 vv = Vr[k4];
                acc += vv.x * Fcol[4 * k4 + 0];
                acc += vv.y * Fcol[4 * k4 + 1];
                acc += vv.z * Fcol[4 * k4 + 2];
                acc += vv.w * Fcol[4 * k4 + 3];
            }
            VF[i][lane] = acc;
        }
        __syncthreads();

        // ---- Phase B: G = C + F^T VF (+reg), fused q partials (C read ONCE) ----
        float VFr[NXd];
        #pragma unroll
        for (int k = 0; k < NXd; k++) VFr[k] = VF[k][lane];
        float Crow[8], zrow[8];
        #pragma unroll
        for (int r = 0; r < 8; r++) {
            int m = 8 * wid + r;
            Crow[r] = Cb[m * NNd + lane];  // MLP=8 prefetch
            zrow[r] = zS[m];
        }
        float qp = 0.f;
        #pragma unroll
        for (int r = 0; r < 8; r++) {
            const int m = 8 * wid + r;
            const float4* Fr = (const float4*)&Ft[m][0];
            float acc = Crow[r];
            #pragma unroll
            for (int k4 = 0; k4 < 6; k4++) {
                float4 f = Fr[k4];
                acc += f.x * VFr[4 * k4 + 0];
                acc += f.y * VFr[4 * k4 + 1];
                acc += f.z * VFr[4 * k4 + 2];
                acc += f.w * VFr[4 * k4 + 3];
            }
            if (m >= NXd && lane == m) acc += REGU;
            G[m][lane] = acc;
            qp += Crow[r] * zrow[r];                       // q[n] -= C[m][n] z[m] (C symmetric)
            if (m >= NXd && lane < NXd) QuxT[lane][m - NXd] = acc;
        }
        qpart[wid][lane] = qp;
        __syncthreads();

        // ---- Phase C: warp0 = Quu^{-1} + K ; warp1 = q, Qxq ----
        if (wid == 0) {
            const unsigned FULL = 0xffffffffu;
            const int r = lane >> 2, cb = lane & 3;  // row r, cols {cb,cb+4} of [Quu|I]
            float a[4];
            a[0] = G[NXd + r][NXd + cb];
            a[1] = G[NXd + r][NXd + cb + 4];
            a[2] = (cb == r)     ? 1.f : 0.f;
            a[3] = (cb + 4 == r) ? 1.f : 0.f;
            #pragma unroll
            for (int k = 0; k < 8; k++) {
                float piv  = __shfl_sync(FULL, a[k >> 2], 4 * k + (k & 3));
                float pinv = 1.0f / piv;
                if (r == k) { a[0] *= pinv; a[1] *= pinv; a[2] *= pinv; a[3] *= pinv; }
                float rk0 = __shfl_sync(FULL, a[0], 4 * k + cb);
                float rk1 = __shfl_sync(FULL, a[1], 4 * k + cb);
                float rk2 = __shfl_sync(FULL, a[2], 4 * k + cb);
                float rk3 = __shfl_sync(FULL, a[3], 4 * k + cb);
                float f   = __shfl_sync(FULL, a[k >> 2], 4 * r + (k & 3));
                if (r != k) { a[0] -= f * rk0; a[1] -= f * rk1; a[2] -= f * rk2; a[3] -= f * rk3; }
            }
            Minv[r][cb]     = a[2];
            Minv[r][cb + 4] = a[3];
            __syncwarp();
            // K = -Minv * Qux : register-cache this thread's QuxT row
            float QT[8];
            if (lane < NXd) {
                const float4* qt = (const float4*)&QuxT[lane][0];
                float4 q0 = qt[0], q1 = qt[1];
                QT[0] = q0.x; QT[1] = q0.y; QT[2] = q0.z; QT[3] = q0.w;
                QT[4] = q1.x; QT[5] = q1.y; QT[6] = q1.z; QT[7] = q1.w;
            }
            #pragma unroll
            for (int l = 0; l < NUd; l++) {
                const float4* Mr = (const float4*)&Minv[l][0];
                float4 m0 = Mr[0], m1 = Mr[1];
                if (lane < NXd) {
                    float acc = m0.x * QT[0] + m0.y * QT[1] + m0.z * QT[2] + m0.w * QT[3]
                              + m1.x * QT[4] + m1.y * QT[5] + m1.z * QT[6] + m1.w * QT[7];
                    float kk = -acc;
                    Kt[l][lane] = kk;
                    g_K[(((size_t)b * Td + t) * NUd + l) * NXd + lane] = kk;
                }
            }
        } else if (wid == 1) {
            float q = cv[((size_t)b * Td + t) * NNd + lane]
                    - (qpart[0][lane] + qpart[1][lane] + qpart[2][lane] + qpart[3][lane]);
            const float4* v4 = (const float4*)vS;
            float acc = q;
            #pragma unroll
            for (int k4 = 0; k4 < 6; k4++) {
                float4 vv = v4[k4];
                acc += vv.x * Fcol[4 * k4 + 0];
                acc += vv.y * Fcol[4 * k4 + 1];
                acc += vv.z * Fcol[4 * k4 + 2];
                acc += vv.w * Fcol[4 * k4 + 3];
            }
            Qxq[lane] = acc;  // Qxq = q + F^T v
        }
        __syncthreads();

        // ---- Phase D: kv (warp0, lanes<8) + Vtmp = Qxx + Qux^T K ----
        if (wid == 0 && lane < NUd) {
            const float4* Mr = (const float4*)&Minv[lane][0];
            float4 m0 = Mr[0], m1 = Mr[1];
            float acc = m0.x * Qxq[NXd + 0] + m0.y * Qxq[NXd + 1]
                      + m0.z * Qxq[NXd + 2] + m0.w * Qxq[NXd + 3]
                      + m1.x * Qxq[NXd + 4] + m1.y * Qxq[NXd + 5]
                      + m1.z * Qxq[NXd + 6] + m1.w * Qxq[NXd + 7];
            kvt[lane] = -acc;
            g_kv[((size_t)b * Td + t) * NUd + lane] = -acc;
        }
        {
            float Kr[8];
            #pragma unroll
            for (int l = 0; l < NUd; l++) Kr[l] = (lane < NXd) ? Kt[l][lane] : 0.f;
            for (int i = wid; i < NXd; i += 4) {
                const float4* qt = (const float4*)&QuxT[i][0];
                float4 u0 = qt[0], u1 = qt[1];
                if (lane < NXd) {
                    float acc = G[i][lane];
                    acc += u0.x * Kr[0] + u0.y * Kr[1] + u0.z * Kr[2] + u0.w * Kr[3]
                         + u1.x * Kr[4] + u1.y * Kr[5] + u1.z * Kr[6] + u1.w * Kr[7];
                    Vtmp[i][lane] = acc;
                }
            }
        }
        __syncthreads();

        // ---- Phase E: symmetrize V, v update, prefetch next zref ----
        for (int o = tid; o < NXd * NXd; o += NTHREADS) {
            int i = o / NXd, j = o - i * NXd;
            V[i][j] = 0.5f * (Vtmp[i][j] + Vtmp[j][i]);
        }
        if (wid == 1 && lane < NXd) {
            const float4* qt = (const float4*)&QuxT[lane][0];
            float4 u0 = qt[0], u1 = qt[1];
            vS[lane] = Qxq[lane]
                     + u0.x * kvt[0] + u0.y * kvt[1] + u0.z * kvt[2] + u0.w * kvt[3]
                     + u1.x * kvt[4] + u1.y * kvt[5] + u1.z * kvt[6] + u1.w * kvt[7];
        }
        if (t > 0 && wid == 2 && lane < NNd) {
            zS[lane] = (lane < NXd) ? xref[((size_t)b * (Td + 1) + (t - 1)) * NXd + lane]
                                    : uref[((size_t)b * Td + (t - 1)) * NUd + (lane - NXd)];
        }
        __syncthreads();
    }

    // ================= forward rollout (warp 0) =================
    if (wid == 0) {
        const unsigned FULL = 0xffffffffu;
        float* ob = out + (size_t)b * ((Td + 1) * NXd + Td * NUd);
        float xv = (lane < NXd) ? x0g[(size_t)b * NXd + lane] : 0.f;
        for (int t = 0; t < Td; t++) {
            if (lane < NXd) ob[t * NXd + lane] = xv;
            // u = K x + k  (lanes 8..31 compute duplicates of lane&7)
            const int l = lane & 7;
            const float* Krow = g_K + (((size_t)b * Td + t) * NUd + l) * NXd;
            float u = g_kv[((size_t)b * Td + t) * NUd + l];
            #pragma unroll
            for (int k = 0; k < NXd; k++) u += Krow[k] * __shfl_sync(FULL, xv, k);
            if (lane < NUd) ob[(Td + 1) * NXd + t * NUd + lane] = u;
            // x' = A x + B u   (A[i][k] = Ft[k][i], B[i][l] = Ft[24+l][i])
            const int i = (lane < NXd) ? lane : 0;
            float acc = 0.f;
            #pragma unroll
            for (int k = 0; k < NXd; k++) acc += Ft[k][i] * __shfl_sync(FULL, xv, k);
            #pragma unroll
            for (int l2 = 0; l2 < NUd; l2++) acc += Ft[NXd + l2][i] * __shfl_sync(FULL, u, l2);
            xv = acc;
        }
        if (lane < NXd) ob[Td * NXd + lane] = xv;
    }
}

extern "C" void kernel_launch(void* const* d_in, const int* in_sizes, int n_in,
                              void* d_out, int out_size)
{
    const float *x0 = nullptr, *C = nullptr, *c = nullptr, *Cf = nullptr, *cf = nullptr;
    const float *xr = nullptr, *ur = nullptr, *A = nullptr, *B = nullptr;
    for (int i = 0; i < n_in; i++) {
        const float* p = (const float*)d_in[i];
        switch (in_sizes[i]) {
            case 512 * 24:              x0 = p; break;
            case 512 * 100 * 32 * 32:   C  = p; break;
            case 512 * 100 * 32:        c  = p; break;
            case 512 * 32 * 32:         Cf = p; break;
            case 512 * 32:              cf = p; break;
            case 512 * 101 * 24:        xr = p; break;
            case 512 * 100 * 8:         ur = p; break;
            case 24 * 24:               A  = p; break;
            case 24 * 8:                B  = p; break;
            default: break;
        }
    }
    if (!x0 || !C || !c || !Cf || !cf || !xr || !ur || !A || !B) {
        x0 = (const float*)d_in[0]; C  = (const float*)d_in[1];
        c  = (const float*)d_in[2]; Cf = (const float*)d_in[3];
        cf = (const float*)d_in[4]; xr = (const float*)d_in[5];
        ur = (const float*)d_in[6]; A  = (const float*)d_in[7];
        B  = (const float*)d_in[8];
    }
    lqr_kernel<<<Bd, NTHREADS>>>(x0, C, c, Cf, cf, xr, ur, A, B, (float*)d_out);
}

// round 6
// speedup vs baseline: 1.8545x; 1.1789x over previous
#include <cuda_runtime.h>
#include <cstdint>

#define NXd 24
#define NUd 8
#define NNd 32
#define Td  100
#define Bd  512
#define NTHREADS 128
#define REGU 1e-6f

// Global scratch for gains (41 MB -> L2-resident).
__device__ float g_K[(size_t)Bd * Td * NUd * NXd];
__device__ float g_kv[(size_t)Bd * Td * NUd];

// ---- packed fp32x2 helpers (Blackwell) ----
__device__ __forceinline__ unsigned long long pack2(float lo, float hi) {
    unsigned long long r;
    asm("mov.b64 %0, {%1, %2};" : "=l"(r) : "f"(lo), "f"(hi));
    return r;
}
__device__ __forceinline__ void ffma2(unsigned long long& acc, unsigned long long a, unsigned long long b) {
    asm("fma.rn.f32x2 %0, %1, %2, %0;" : "+l"(acc) : "l"(a), "l"(b));
}
__device__ __forceinline__ float sum2(unsigned long long a) {
    float lo, hi;
    asm("mov.b64 {%0, %1}, %2;" : "=f"(lo), "=f"(hi) : "l"(a));
    return lo + hi;
}
__device__ __forceinline__ unsigned long long d2ll(double d) { return __double_as_longlong(d); }

__device__ __forceinline__ void cp_async16(uint32_t dst, const void* src) {
    asm volatile("cp.async.cg.shared.global [%0], [%1], 16;" :: "r"(dst), "l"(src) : "memory");
}

__global__ __launch_bounds__(NTHREADS, 4)
void lqr_kernel(const float* __restrict__ x0g,
                const float* __restrict__ Cm,
                const float* __restrict__ cv,
                const float* __restrict__ Cf,
                const float* __restrict__ cf,
                const float* __restrict__ xref,
                const float* __restrict__ uref,
                const float* __restrict__ Ad,
                const float* __restrict__ Bdyn,
                float* __restrict__ out)
{
    __shared__ __align__(16) float Ft[NNd][NXd];     // Ft[m][k] = F[k][m]
    __shared__ __align__(16) float V[NXd][NXd];      // symmetric value matrix
    __shared__ __align__(16) float Vtmp[NXd][25];    // padded: conflict-free transpose read
    __shared__ __align__(16) float VF[NXd][NNd];     // V * F
    __shared__ __align__(16) float G[NNd][NNd];      // C_t + F^T V F (+reg)
    __shared__ __align__(16) float QuxT[NXd][NUd];   // QuxT[j][l] = G[24+l][j]
    __shared__ __align__(16) float zS[NNd];          // async-filled zref
    __shared__ __align__(16) float Cbuf[NNd][NNd];   // async-staged C tile
    __shared__ __align__(16) float cvbuf[NNd];       // async-staged cv slice
    __shared__ __align__(16) float qpart[4][NNd];
    __shared__ __align__(16) float Qxq[NNd];         // [Qx (24) | Qu (8)]
    __shared__ __align__(16) float vS[NXd];
    __shared__ __align__(16) float Minv[NUd][NUd];
    __shared__ __align__(16) float Kt[NUd][NXd];
    __shared__ __align__(16) float kvt[NUd];

    const int b    = blockIdx.x;
    const int tid  = threadIdx.x;
    const int wid  = tid >> 5;
    const int lane = tid & 31;

    const uint32_t cbuf_a = (uint32_t)__cvta_generic_to_shared(&Cbuf[0][0]);
    const uint32_t cvb_a  = (uint32_t)__cvta_generic_to_shared(&cvbuf[0]);
    const uint32_t zs_a   = (uint32_t)__cvta_generic_to_shared(&zS[0]);

    // ---- register-resident packed F column: Fcol2[p] = {F[2p][lane], F[2p+1][lane]} ----
    unsigned long long Fcol2[12];
    {
        float fc[NXd];
        #pragma unroll
        for (int k = 0; k < NXd; k++)
            fc[k] = (lane < NXd) ? Ad[k * NXd + lane] : Bdyn[k * NUd + (lane - NXd)];
        #pragma unroll
        for (int p = 0; p < 12; p++) Fcol2[p] = pack2(fc[2 * p], fc[2 * p + 1]);
    }

    // ---- async prologue fill for t = T-1: C tile, cv slice, zref ----
    {
        const int t0 = Td - 1;
        const char* Csrc = (const char*)(Cm + ((size_t)b * Td + t0) * NNd * NNd);
        cp_async16(cbuf_a + tid * 16, Csrc + tid * 16);
        cp_async16(cbuf_a + tid * 16 + 2048, Csrc + tid * 16 + 2048);
        if (tid < 8) {
            cp_async16(cvb_a + tid * 16,
                       (const char*)(cv + ((size_t)b * Td + t0) * NNd) + tid * 16);
        } else if (tid < 14) {
            int j = tid - 8;
            cp_async16(zs_a + j * 16,
                       (const char*)(xref + ((size_t)b * (Td + 1) + t0) * NXd) + j * 16);
        } else if (tid < 16) {
            int j = tid - 14;
            cp_async16(zs_a + 96 + j * 16,
                       (const char*)(uref + ((size_t)b * Td + t0) * NUd) + j * 16);
        }
        asm volatile("cp.async.commit_group;" ::: "memory");
    }

    // ---- init: Ft smem ----
    for (int o = tid; o < NXd * NNd; o += NTHREADS) {
        int k = o >> 5, m = o & 31;
        Ft[m][k] = (m < NXd) ? Ad[k * NXd + m] : Bdyn[k * NUd + (m - NXd)];
    }
    // ---- init: V = C_final[:24,:24] ----
    for (int o = tid; o < NXd * NXd; o += NTHREADS) {
        int i = o / NXd, j = o - i * NXd;
        V[i][j] = Cf[((size_t)b * NNd + i) * NNd + j];
    }
    __syncthreads();
    // ---- v_T = c_final[:24] - V @ x_ref[:,T] ----
    if (tid < NXd) {
        float acc = cf[(size_t)b * NNd + tid];
        const float* xl = xref + ((size_t)b * (Td + 1) + Td) * NXd;
        #pragma unroll
        for (int j = 0; j < NXd; j++) acc -= V[tid][j] * xl[j];
        vS[tid] = acc;
    }
    __syncthreads();

    // ================= backward Riccati =================
    for (int t = Td - 1; t >= 0; t--) {
        // ---- Phase A: VF[i][lane] = sum_k V[i][k] F[k][lane]  (packed) ----
        for (int i = wid; i < NXd; i += 4) {
            const double2* Vr = (const double2*)&V[i][0];
            unsigned long long acc = 0ULL;
            #pragma unroll
            for (int j = 0; j < 6; j++) {
                double2 vv = Vr[j];
                ffma2(acc, d2ll(vv.x), Fcol2[2 * j]);
                ffma2(acc, d2ll(vv.y), Fcol2[2 * j + 1]);
            }
            VF[i][lane] = sum2(acc);
        }
        asm volatile("cp.async.wait_group 0;" ::: "memory");
        __syncthreads();

        // ---- Phase B: G = C + F^T VF (+reg), fused q partials ----
        const float cvq = cvbuf[lane];  // read before refill race window
        unsigned long long VFr2[12];
        #pragma unroll
        for (int p = 0; p < 12; p++) VFr2[p] = pack2(VF[2 * p][lane], VF[2 * p + 1][lane]);
        float qp = 0.f;
        #pragma unroll
        for (int r = 0; r < 8; r++) {
            const int m = 8 * wid + r;
            const float Cval = Cbuf[m][lane];
            const double2* Fr = (const double2*)&Ft[m][0];
            unsigned long long acc = 0ULL;
            #pragma unroll
            for (int j = 0; j < 6; j++) {
                double2 ff = Fr[j];
                ffma2(acc, d2ll(ff.x), VFr2[2 * j]);
                ffma2(acc, d2ll(ff.y), VFr2[2 * j + 1]);
            }
            float g = Cval + sum2(acc);
            if (m >= NXd && lane == m) g += REGU;
            G[m][lane] = g;
            qp += Cval * zS[m];                           // C symmetric: q via column dot
            if (m >= NXd && lane < NXd) QuxT[lane][m - NXd] = g;
        }
        qpart[wid][lane] = qp;
        __syncthreads();

        // ---- async fill for t-1 (consumed next iter; covered by C/D/E/A) ----
        if (t > 0) {
            const int tn = t - 1;
            const char* Csrc = (const char*)(Cm + ((size_t)b * Td + tn) * NNd * NNd);
            cp_async16(cbuf_a + tid * 16, Csrc + tid * 16);
            cp_async16(cbuf_a + tid * 16 + 2048, Csrc + tid * 16 + 2048);
            if (tid < 8) {
                cp_async16(cvb_a + tid * 16,
                           (const char*)(cv + ((size_t)b * Td + tn) * NNd) + tid * 16);
            } else if (tid < 14) {
                int j = tid - 8;
                cp_async16(zs_a + j * 16,
                           (const char*)(xref + ((size_t)b * (Td + 1) + tn) * NXd) + j * 16);
            } else if (tid < 16) {
                int j = tid - 14;
                cp_async16(zs_a + 96 + j * 16,
                           (const char*)(uref + ((size_t)b * Td + tn) * NUd) + j * 16);
            }
            asm volatile("cp.async.commit_group;" ::: "memory");
        }

        // ---- Phase C: warp0 = Quu^{-1} + K ; warp1 = Qxq ----
        if (wid == 0) {
            const unsigned FULL = 0xffffffffu;
            const int r = lane >> 2, cb = lane & 3;
            float a[4];
            a[0] = G[NXd + r][NXd + cb];
            a[1] = G[NXd + r][NXd + cb + 4];
            a[2] = (cb == r)     ? 1.f : 0.f;
            a[3] = (cb + 4 == r) ? 1.f : 0.f;
            #pragma unroll
            for (int k = 0; k < 8; k++) {
                float piv  = __shfl_sync(FULL, a[k >> 2], 4 * k + (k & 3));
                float pinv = 1.0f / piv;
                if (r == k) { a[0] *= pinv; a[1] *= pinv; a[2] *= pinv; a[3] *= pinv; }
                float rk0 = __shfl_sync(FULL, a[0], 4 * k + cb);
                float rk1 = __shfl_sync(FULL, a[1], 4 * k + cb);
                float rk2 = __shfl_sync(FULL, a[2], 4 * k + cb);
                float rk3 = __shfl_sync(FULL, a[3], 4 * k + cb);
                float f   = __shfl_sync(FULL, a[k >> 2], 4 * r + (k & 3));
                if (r != k) { a[0] -= f * rk0; a[1] -= f * rk1; a[2] -= f * rk2; a[3] -= f * rk3; }
            }
            Minv[r][cb]     = a[2];
            Minv[r][cb + 4] = a[3];
            __syncwarp();
            const int jl = (lane < NXd) ? lane : 0;
            const double2* qt = (const double2*)&QuxT[jl][0];
            double2 q0 = qt[0], q1 = qt[1];
            unsigned long long QT2[4] = { d2ll(q0.x), d2ll(q0.y), d2ll(q1.x), d2ll(q1.y) };
            #pragma unroll
            for (int l = 0; l < NUd; l++) {
                const double2* Mr = (const double2*)&Minv[l][0];
                double2 m0 = Mr[0], m1 = Mr[1];
                unsigned long long acc = 0ULL;
                ffma2(acc, d2ll(m0.x), QT2[0]);
                ffma2(acc, d2ll(m0.y), QT2[1]);
                ffma2(acc, d2ll(m1.x), QT2[2]);
                ffma2(acc, d2ll(m1.y), QT2[3]);
                if (lane < NXd) {
                    float kk = -sum2(acc);
                    Kt[l][lane] = kk;
                    g_K[(((size_t)b * Td + t) * NUd + l) * NXd + lane] = kk;
                }
            }
        } else if (wid == 1) {
            float q = cvq - (qpart[0][lane] + qpart[1][lane] + qpart[2][lane] + qpart[3][lane]);
            const double2* v2 = (const double2*)vS;
            unsigned long long acc = 0ULL;
            #pragma unroll
            for (int j = 0; j < 6; j++) {
                double2 vv = v2[j];
                ffma2(acc, d2ll(vv.x), Fcol2[2 * j]);
                ffma2(acc, d2ll(vv.y), Fcol2[2 * j + 1]);
            }
            Qxq[lane] = q + sum2(acc);  // Qxq = q + F^T v
        }
        __syncthreads();

        // ---- Phase D: kv (warp0 lanes<8) + Vtmp = Qxx + Qux^T K ----
        if (wid == 0 && lane < NUd) {
            const double2* Mr = (const double2*)&Minv[lane][0];
            double2 m0 = Mr[0], m1 = Mr[1];
            const double2* Qu2 = (const double2*)&Qxq[NXd];
            double2 u0 = Qu2[0], u1 = Qu2[1];
            unsigned long long acc = 0ULL;
            ffma2(acc, d2ll(m0.x), d2ll(u0.x));
            ffma2(acc, d2ll(m0.y), d2ll(u0.y));
            ffma2(acc, d2ll(m1.x), d2ll(u1.x));
            ffma2(acc, d2ll(m1.y), d2ll(u1.y));
            float kvv = -sum2(acc);
            kvt[lane] = kvv;
            g_kv[((size_t)b * Td + t) * NUd + lane] = kvv;
        }
        {
            const int jl = (lane < NXd) ? lane : 0;
            unsigned long long Kr2[4];
            #pragma unroll
            for (int p = 0; p < 4; p++) Kr2[p] = pack2(Kt[2 * p][jl], Kt[2 * p + 1][jl]);
            for (int i = wid; i < NXd; i += 4) {
                const double2* qt = (const double2*)&QuxT[i][0];
                double2 q0 = qt[0], q1 = qt[1];
                unsigned long long acc = 0ULL;
                ffma2(acc, d2ll(q0.x), Kr2[0]);
                ffma2(acc, d2ll(q0.y), Kr2[1]);
                ffma2(acc, d2ll(q1.x), Kr2[2]);
                ffma2(acc, d2ll(q1.y), Kr2[3]);
                if (lane < NXd) Vtmp[i][lane] = G[i][lane] + sum2(acc);
            }
        }
        __syncthreads();

        // ---- Phase E: symmetrize V, v update ----
        for (int o = tid; o < NXd * NXd; o += NTHREADS) {
            int i = o / NXd, j = o - i * NXd;
            V[i][j] = 0.5f * (Vtmp[i][j] + Vtmp[j][i]);
        }
        if (wid == 1 && lane < NXd) {
            const double2* qt = (const double2*)&QuxT[lane][0];
            double2 q0 = qt[0], q1 = qt[1];
            const double2* kv2 = (const double2*)kvt;
            double2 k0 = kv2[0], k1 = kv2[1];
            unsigned long long acc = 0ULL;
            ffma2(acc, d2ll(q0.x), d2ll(k0.x));
            ffma2(acc, d2ll(q0.y), d2ll(k0.y));
            ffma2(acc, d2ll(q1.x), d2ll(k1.x));
            ffma2(acc, d2ll(q1.y), d2ll(k1.y));
            vS[lane] = Qxq[lane] + sum2(acc);
        }
        __syncthreads();
    }

    // ================= forward rollout (warp 0) =================
    if (wid == 0) {
        const unsigned FULL = 0xffffffffu;
        float* ob = out + (size_t)b * ((Td + 1) * NXd + Td * NUd);
        float xv = (lane < NXd) ? x0g[(size_t)b * NXd + lane] : 0.f;
        for (int t = 0; t < Td; t++) {
            if (lane < NXd) ob[t * NXd + lane] = xv;
            const int l = lane & 7;
            const float* Krow = g_K + (((size_t)b * Td + t) * NUd + l) * NXd;
            float u = g_kv[((size_t)b * Td + t) * NUd + l];
            #pragma unroll
            for (int k = 0; k < NXd; k++) u += Krow[k] * __shfl_sync(FULL, xv, k);
            if (lane < NUd) ob[(Td + 1) * NXd + t * NUd + lane] = u;
            const int i = (lane < NXd) ? lane : 0;
            float acc = 0.f;
            #pragma unroll
            for (int k = 0; k < NXd; k++) acc += Ft[k][i] * __shfl_sync(FULL, xv, k);
            #pragma unroll
            for (int l2 = 0; l2 < NUd; l2++) acc += Ft[NXd + l2][i] * __shfl_sync(FULL, u, l2);
            xv = acc;
        }
        if (lane < NXd) ob[Td * NXd + lane] = xv;
    }
}

extern "C" void kernel_launch(void* const* d_in, const int* in_sizes, int n_in,
                              void* d_out, int out_size)
{
    const float *x0 = nullptr, *C = nullptr, *c = nullptr, *Cf = nullptr, *cf = nullptr;
    const float *xr = nullptr, *ur = nullptr, *A = nullptr, *B = nullptr;
    for (int i = 0; i < n_in; i++) {
        const float* p = (const float*)d_in[i];
        switch (in_sizes[i]) {
            case 512 * 24:              x0 = p; break;
            case 512 * 100 * 32 * 32:   C  = p; break;
            case 512 * 100 * 32:        c  = p; break;
            case 512 * 32 * 32:         Cf = p; break;
            case 512 * 32:              cf = p; break;
            case 512 * 101 * 24:        xr = p; break;
            case 512 * 100 * 8:         ur = p; break;
            case 24 * 24:               A  = p; break;
            case 24 * 8:                B  = p; break;
            default: break;
        }
    }
    if (!x0 || !C || !c || !Cf || !cf || !xr || !ur || !A || !B) {
        x0 = (const float*)d_in[0]; C  = (const float*)d_in[1];
        c  = (const float*)d_in[2]; Cf = (const float*)d_in[3];
        cf = (const float*)d_in[4]; xr = (const float*)d_in[5];
        ur = (const float*)d_in[6]; A  = (const float*)d_in[7];
        B  = (const float*)d_in[8];
    }
    lqr_kernel<<<Bd, NTHREADS>>>(x0, C, c, Cf, cf, xr, ur, A, B, (float*)d_out);
}